// round 1
// baseline (speedup 1.0000x reference)
#include <cuda_runtime.h>
#include <cstdint>
#include <cstddef>

#define NROWS 8192
#define INDIM 2029
#define DDIM  128

// Scratch (device globals — no allocation allowed)
__device__ float g_qkv[NROWS * 1152];   // [n][9 segs][128]; segs: Vq,Vk,Vv, Aq,Ak,Av, Tq,Tk,Tv
__device__ float g_att[NROWS * 384];    // [n][attT | attA | attV]

struct WPtrs { const float* w[9]; };

__device__ __forceinline__ unsigned long long pack2(float x) {
    unsigned long long r;
    asm("mov.b64 %0, {%1, %1};" : "=l"(r) : "f"(x));
    return r;
}
__device__ __forceinline__ unsigned long long fma2(unsigned long long a,
                                                   unsigned long long b,
                                                   unsigned long long c) {
    unsigned long long d;
    asm("fma.rn.f32x2 %0, %1, %2, %3;" : "=l"(d) : "l"(a), "l"(b), "l"(c));
    return d;
}
__device__ __forceinline__ float ex2f(float x) {
    float r;
    asm("ex2.approx.f32 %0, %1;" : "=f"(r) : "f"(x));
    return r;
}

// ---------------------------------------------------------------------------
// Kernel 1: QKV projections. C[128x128] tile per block, K varies per segment.
// Packed f32x2 FMA micro-kernel: 8 rows x 8 cols (4 u64 pairs) per thread.
// ---------------------------------------------------------------------------
__global__ __launch_bounds__(256, 2)
void qkv_gemm_kernel(const float* __restrict__ h, WPtrs wp) {
    const int Ks[9]   = {1587,1587,1587, 342,342,342, 100,100,100};
    const int Hoff[9] = { 442, 442, 442, 100,100,100,   0,  0,  0};
    const int s    = blockIdx.y;
    const int K    = Ks[s];
    const int hoff = Hoff[s];
    const float* __restrict__ W = wp.w[s];
    const int n0 = blockIdx.x * 128;

    __shared__ __align__(16) float As[16][132];
    __shared__ __align__(16) float Bs[16][132];

    const int tid = threadIdx.x;
    const int tm  = tid >> 4;   // 0..15 -> rows tm*8..tm*8+7
    const int tn  = tid & 15;   // 0..15 -> cols 4tn..4tn+3 and 64+4tn..64+4tn+3
    const int lk  = tid & 15;   // load k index
    const int lr  = tid >> 4;   // load row group

    unsigned long long acc[8][4];
#pragma unroll
    for (int i = 0; i < 8; i++)
#pragma unroll
        for (int j = 0; j < 4; j++) acc[i][j] = 0ULL;

    for (int k0 = 0; k0 < K; k0 += 16) {
        const int kk_g = k0 + lk;
        const bool kv = (kk_g < K);
#pragma unroll
        for (int r = 0; r < 8; r++) {
            int m = r * 16 + lr;
            As[lk][m] = kv ? h[(size_t)(n0 + m) * INDIM + hoff + kk_g] : 0.0f;
        }
#pragma unroll
        for (int r = 0; r < 8; r++) {
            int dd = r * 16 + lr;
            Bs[lk][dd] = kv ? W[(size_t)dd * K + kk_g] : 0.0f;
        }
        __syncthreads();

#pragma unroll
        for (int kk = 0; kk < 16; kk++) {
            float4 a0 = *reinterpret_cast<const float4*>(&As[kk][tm * 8]);
            float4 a1 = *reinterpret_cast<const float4*>(&As[kk][tm * 8 + 4]);
            float4 b0 = *reinterpret_cast<const float4*>(&Bs[kk][tn * 4]);
            float4 b1 = *reinterpret_cast<const float4*>(&Bs[kk][64 + tn * 4]);
            unsigned long long bp[4];
            bp[0] = reinterpret_cast<const unsigned long long*>(&b0)[0];
            bp[1] = reinterpret_cast<const unsigned long long*>(&b0)[1];
            bp[2] = reinterpret_cast<const unsigned long long*>(&b1)[0];
            bp[3] = reinterpret_cast<const unsigned long long*>(&b1)[1];
            float av[8] = {a0.x, a0.y, a0.z, a0.w, a1.x, a1.y, a1.z, a1.w};
#pragma unroll
            for (int mi = 0; mi < 8; mi++) {
                unsigned long long ap = pack2(av[mi]);
#pragma unroll
                for (int p = 0; p < 4; p++)
                    acc[mi][p] = fma2(ap, bp[p], acc[mi][p]);
            }
        }
        __syncthreads();
    }

#pragma unroll
    for (int mi = 0; mi < 8; mi++) {
        float* crow = g_qkv + (size_t)(n0 + tm * 8 + mi) * 1152 + s * 128;
#pragma unroll
        for (int p = 0; p < 4; p++) {
            float2 c = *reinterpret_cast<float2*>(&acc[mi][p]);
            int d = (p < 2) ? (tn * 4 + p * 2) : (64 + tn * 4 + (p - 2) * 2);
            *reinterpret_cast<float2*>(crow + d) = c;
        }
    }
}

// ---------------------------------------------------------------------------
// Kernel 2: per-(node,unit) attention.
// E[i][j] = exp2(qs_i * k_j), Z_j = sum_i E, out_i = sum_j E[i][j] * v_j/Z_j
// blockIdx.y: 0=V, 1=A, 2=T (matches qkv seg order); att output T|A|V.
// ---------------------------------------------------------------------------
__global__ void attn_kernel() {
    extern __shared__ __align__(16) float sm[];
    float* qs = sm;             // 128
    float* w  = sm + 128;       // 128
    float* E  = sm + 256;       // 128 * 132

    const int n = blockIdx.x;
    const int u = blockIdx.y;   // 0=V, 1=A, 2=T
    const int j = threadIdx.x;  // column in phase1, row in phase2

    const float* base = g_qkv + (size_t)n * 1152 + u * 384;
    const float qj = base[j];
    const float kj = base[128 + j];
    const float vj = base[256 + j];

    // log2(e) / sqrt(128)
    const float scale = 1.4426950408889634f / 11.313708498984761f;
    qs[j] = qj * scale;
    __syncthreads();

    float Z = 0.0f;
#pragma unroll 8
    for (int i = 0; i < 128; i++) {
        float e = ex2f(qs[i] * kj);
        Z += e;
        E[i * 132 + j] = e;
    }
    w[j] = vj / Z;
    __syncthreads();

    float out = 0.0f;
    const float4* Er = reinterpret_cast<const float4*>(E + j * 132);
    const float4* w4 = reinterpret_cast<const float4*>(w);
#pragma unroll 8
    for (int t = 0; t < 32; t++) {
        float4 e4 = Er[t];
        float4 wv = w4[t];
        out += e4.x * wv.x + e4.y * wv.y + e4.z * wv.z + e4.w * wv.w;
    }
    const int attoff = (2 - u) * 128;  // V->256, A->128, T->0
    g_att[(size_t)n * 384 + attoff + j] = out;
}

// ---------------------------------------------------------------------------
// Kernel 3: out = att @ Wln.T + bln.  C[64x128] per block, K=384.
// ---------------------------------------------------------------------------
__global__ __launch_bounds__(256, 4)
void out_gemm_kernel(const float* __restrict__ Wln, const float* __restrict__ bln,
                     float* __restrict__ out) {
    __shared__ __align__(16) float As[16][68];
    __shared__ __align__(16) float Bs[16][132];

    const int n0 = blockIdx.x * 64;
    const int tid = threadIdx.x;
    const int tm  = tid >> 4;   // rows tm*4..tm*4+3
    const int tn  = tid & 15;
    const int lk  = tid & 15;
    const int lr  = tid >> 4;

    unsigned long long acc[4][4];
#pragma unroll
    for (int i = 0; i < 4; i++)
#pragma unroll
        for (int j = 0; j < 4; j++) acc[i][j] = 0ULL;

    for (int k0 = 0; k0 < 384; k0 += 16) {
#pragma unroll
        for (int r = 0; r < 4; r++) {
            int m = r * 16 + lr;
            As[lk][m] = g_att[(size_t)(n0 + m) * 384 + k0 + lk];
        }
#pragma unroll
        for (int r = 0; r < 8; r++) {
            int dd = r * 16 + lr;
            Bs[lk][dd] = Wln[(size_t)dd * 384 + k0 + lk];
        }
        __syncthreads();

#pragma unroll
        for (int kk = 0; kk < 16; kk++) {
            float4 a0 = *reinterpret_cast<const float4*>(&As[kk][tm * 4]);
            float4 b0 = *reinterpret_cast<const float4*>(&Bs[kk][tn * 4]);
            float4 b1 = *reinterpret_cast<const float4*>(&Bs[kk][64 + tn * 4]);
            unsigned long long bp[4];
            bp[0] = reinterpret_cast<const unsigned long long*>(&b0)[0];
            bp[1] = reinterpret_cast<const unsigned long long*>(&b0)[1];
            bp[2] = reinterpret_cast<const unsigned long long*>(&b1)[0];
            bp[3] = reinterpret_cast<const unsigned long long*>(&b1)[1];
            float av[4] = {a0.x, a0.y, a0.z, a0.w};
#pragma unroll
            for (int mi = 0; mi < 4; mi++) {
                unsigned long long ap = pack2(av[mi]);
#pragma unroll
                for (int p = 0; p < 4; p++)
                    acc[mi][p] = fma2(ap, bp[p], acc[mi][p]);
            }
        }
        __syncthreads();
    }

#pragma unroll
    for (int mi = 0; mi < 4; mi++) {
        float* crow = out + (size_t)(n0 + tm * 4 + mi) * 128;
#pragma unroll
        for (int p = 0; p < 4; p++) {
            float2 c = *reinterpret_cast<float2*>(&acc[mi][p]);
            int d = (p < 2) ? (tn * 4 + p * 2) : (64 + tn * 4 + (p - 2) * 2);
            c.x += bln[d];
            c.y += bln[d + 1];
            *reinterpret_cast<float2*>(crow + d) = c;
        }
    }
}

// ---------------------------------------------------------------------------
// Input order: 0 g, 1 h, 2 WqT, 3 WkT, 4 WvT, 5 WqA, 6 WkA, 7 WvA,
//              8 WqV, 9 WkV, 10 WvV, 11 Wln, 12 bln
// ---------------------------------------------------------------------------
extern "C" void kernel_launch(void* const* d_in, const int* in_sizes, int n_in,
                              void* d_out, int out_size) {
    const float* h = (const float*)d_in[1];
    WPtrs wp;
    // Heavy V segment first (scheduled first by blockIdx.y order)
    wp.w[0] = (const float*)d_in[8];   // WqV
    wp.w[1] = (const float*)d_in[9];   // WkV
    wp.w[2] = (const float*)d_in[10];  // WvV
    wp.w[3] = (const float*)d_in[5];   // WqA
    wp.w[4] = (const float*)d_in[6];   // WkA
    wp.w[5] = (const float*)d_in[7];   // WvA
    wp.w[6] = (const float*)d_in[2];   // WqT
    wp.w[7] = (const float*)d_in[3];   // WkT
    wp.w[8] = (const float*)d_in[4];   // WvT
    const float* Wln = (const float*)d_in[11];
    const float* bln = (const float*)d_in[12];

    qkv_gemm_kernel<<<dim3(64, 9), 256>>>(h, wp);

    const int smem_bytes = (128 * 132 + 256) * (int)sizeof(float);  // 68608
    cudaFuncSetAttribute(attn_kernel, cudaFuncAttributeMaxDynamicSharedMemorySize,
                         smem_bytes);
    attn_kernel<<<dim3(NROWS, 3), 128, smem_bytes>>>();

    out_gemm_kernel<<<128, 256>>>(Wln, bln, (float*)d_out);
}

// round 3
// speedup vs baseline: 2.0066x; 2.0066x over previous
#include <cuda_runtime.h>
#include <cuda_bf16.h>
#include <cstdint>
#include <cstddef>

#define NROWS 8192
#define INDIM 2029
#define KC 32

// Scratch (device globals — no allocation allowed)
__device__ float g_qkv[NROWS * 1152];   // [n][9 segs][128]; segs: Vq,Vk,Vv, Aq,Ak,Av, Tq,Tk,Tv
__device__ float g_att[NROWS * 384];    // [n][attT | attA | attV]

struct WPtrs { const float* w[9]; };

__device__ __forceinline__ float ex2f(float x) {
    float r; asm("ex2.approx.f32 %0, %1;" : "=f"(r) : "f"(x)); return r;
}

__device__ __forceinline__ void mma16816(float* c, const uint32_t* a, const uint32_t* b) {
    asm volatile(
        "mma.sync.aligned.m16n8k16.row.col.f32.bf16.bf16.f32 "
        "{%0,%1,%2,%3}, {%4,%5,%6,%7}, {%8,%9}, {%0,%1,%2,%3};"
        : "+f"(c[0]), "+f"(c[1]), "+f"(c[2]), "+f"(c[3])
        : "r"(a[0]), "r"(a[1]), "r"(a[2]), "r"(a[3]), "r"(b[0]), "r"(b[1]));
}

// Split 16 floats into bf16 hi/lo pairs, packed 2-per-u32 (even elem in low half).
__device__ __forceinline__ void split_pack(const float* v, uint32_t* hi, uint32_t* lo) {
#pragma unroll
    for (int p = 0; p < 8; p++) {
        float x = v[2 * p], y = v[2 * p + 1];
        __nv_bfloat16 hx = __float2bfloat16(x), hy = __float2bfloat16(y);
        float rx = x - __bfloat162float(hx);
        float ry = y - __bfloat162float(hy);
        __nv_bfloat16 lx = __float2bfloat16(rx), ly = __float2bfloat16(ry);
        hi[p] = ((uint32_t)__bfloat16_as_ushort(hy) << 16) | (uint32_t)__bfloat16_as_ushort(hx);
        lo[p] = ((uint32_t)__bfloat16_as_ushort(ly) << 16) | (uint32_t)__bfloat16_as_ushort(lx);
    }
}

// ---------------------------------------------------------------------------
// Shared GEMM: C[128 x 128] = A[128 x K] * W[128 x K]^T (+ bias), fp32 in/out.
// 3-pass bf16 split via mma.sync m16n8k16. Double-buffered smem, reg prefetch.
// Smem layout per stage (40960 B): Ah | Al | Bh | Bl, each 128 rows x 80 B.
// ---------------------------------------------------------------------------
__device__ __forceinline__ void gemm_mma_128(
    const float* __restrict__ A, int lda, int K,
    const float* __restrict__ W,           // [128][K] row-major
    float* __restrict__ C, int ldc,
    const float* __restrict__ bias, int n0)
{
    extern __shared__ __align__(16) char dsm[];
    const int TB = 10240, STAGE = 40960;

    const int tid  = threadIdx.x;
    const int lane = tid & 31, wid = tid >> 5;
    const int wm = wid & 3, wn = wid >> 2;
    const int g4 = lane >> 2, tq = lane & 3;
    const int lr = tid >> 1, lh = tid & 1;

    float acc[2][8][4];
#pragma unroll
    for (int t = 0; t < 2; t++)
#pragma unroll
        for (int nt = 0; nt < 8; nt++)
#pragma unroll
            for (int i = 0; i < 4; i++) acc[t][nt][i] = 0.0f;

    const float* arow = A + (size_t)(n0 + lr) * lda;
    const float* wrow = W + (size_t)lr * K;

    const int NC = (K + KC - 1) / KC;

    float va[16], vb[16];
    // load chunk 0
    {
        int kb = lh * 16;
#pragma unroll
        for (int i = 0; i < 16; i++) {
            int kg = kb + i; bool ok = kg < K;
            va[i] = ok ? __ldg(arow + kg) : 0.0f;
            vb[i] = ok ? __ldg(wrow + kg) : 0.0f;
        }
    }
    // store chunk 0 -> stage 0
    {
        uint32_t h8[8], l8[8];
        char* base = dsm + lr * 80 + lh * 32;
        split_pack(va, h8, l8);
        *(uint4*)(base +            0) = make_uint4(h8[0], h8[1], h8[2], h8[3]);
        *(uint4*)(base +           16) = make_uint4(h8[4], h8[5], h8[6], h8[7]);
        *(uint4*)(base + TB +       0) = make_uint4(l8[0], l8[1], l8[2], l8[3]);
        *(uint4*)(base + TB +      16) = make_uint4(l8[4], l8[5], l8[6], l8[7]);
        split_pack(vb, h8, l8);
        *(uint4*)(base + 2 * TB +   0) = make_uint4(h8[0], h8[1], h8[2], h8[3]);
        *(uint4*)(base + 2 * TB +  16) = make_uint4(h8[4], h8[5], h8[6], h8[7]);
        *(uint4*)(base + 3 * TB +   0) = make_uint4(l8[0], l8[1], l8[2], l8[3]);
        *(uint4*)(base + 3 * TB +  16) = make_uint4(l8[4], l8[5], l8[6], l8[7]);
    }
    __syncthreads();

    for (int c = 0; c < NC; c++) {
        if (c + 1 < NC) {
            int kb = (c + 1) * KC + lh * 16;
#pragma unroll
            for (int i = 0; i < 16; i++) {
                int kg = kb + i; bool ok = kg < K;
                va[i] = ok ? __ldg(arow + kg) : 0.0f;
                vb[i] = ok ? __ldg(wrow + kg) : 0.0f;
            }
        }

        {
            char* st = dsm + (c & 1) * STAGE;
#pragma unroll
            for (int kk = 0; kk < 2; kk++) {
                const int cb = kk * 32 + tq * 4;
                uint32_t ah[2][4], al[2][4];
#pragma unroll
                for (int t = 0; t < 2; t++) {
                    int r0 = (wm * 32 + t * 16 + g4) * 80;
                    ah[t][0] = *(const uint32_t*)(st + r0 + cb);
                    ah[t][1] = *(const uint32_t*)(st + r0 + 640 + cb);
                    ah[t][2] = *(const uint32_t*)(st + r0 + cb + 16);
                    ah[t][3] = *(const uint32_t*)(st + r0 + 640 + cb + 16);
                    al[t][0] = *(const uint32_t*)(st + TB + r0 + cb);
                    al[t][1] = *(const uint32_t*)(st + TB + r0 + 640 + cb);
                    al[t][2] = *(const uint32_t*)(st + TB + r0 + cb + 16);
                    al[t][3] = *(const uint32_t*)(st + TB + r0 + 640 + cb + 16);
                }
#pragma unroll
                for (int nt = 0; nt < 8; nt++) {
                    int rb = (wn * 64 + nt * 8 + g4) * 80;
                    uint32_t bh[2], bl[2];
                    bh[0] = *(const uint32_t*)(st + 2 * TB + rb + cb);
                    bh[1] = *(const uint32_t*)(st + 2 * TB + rb + cb + 16);
                    bl[0] = *(const uint32_t*)(st + 3 * TB + rb + cb);
                    bl[1] = *(const uint32_t*)(st + 3 * TB + rb + cb + 16);
                    mma16816(acc[0][nt], ah[0], bh);
                    mma16816(acc[1][nt], ah[1], bh);
                    mma16816(acc[0][nt], ah[0], bl);
                    mma16816(acc[1][nt], ah[1], bl);
                    mma16816(acc[0][nt], al[0], bh);
                    mma16816(acc[1][nt], al[1], bh);
                }
            }
        }

        if (c + 1 < NC) {
            uint32_t h8[8], l8[8];
            char* base = dsm + ((c + 1) & 1) * STAGE + lr * 80 + lh * 32;
            split_pack(va, h8, l8);
            *(uint4*)(base +            0) = make_uint4(h8[0], h8[1], h8[2], h8[3]);
            *(uint4*)(base +           16) = make_uint4(h8[4], h8[5], h8[6], h8[7]);
            *(uint4*)(base + TB +       0) = make_uint4(l8[0], l8[1], l8[2], l8[3]);
            *(uint4*)(base + TB +      16) = make_uint4(l8[4], l8[5], l8[6], l8[7]);
            split_pack(vb, h8, l8);
            *(uint4*)(base + 2 * TB +   0) = make_uint4(h8[0], h8[1], h8[2], h8[3]);
            *(uint4*)(base + 2 * TB +  16) = make_uint4(h8[4], h8[5], h8[6], h8[7]);
            *(uint4*)(base + 3 * TB +   0) = make_uint4(l8[0], l8[1], l8[2], l8[3]);
            *(uint4*)(base + 3 * TB +  16) = make_uint4(l8[4], l8[5], l8[6], l8[7]);
        }
        __syncthreads();
    }

#pragma unroll
    for (int t = 0; t < 2; t++)
#pragma unroll
        for (int nt = 0; nt < 8; nt++) {
            int gm = n0 + wm * 32 + t * 16 + g4;
            int gn = wn * 64 + nt * 8 + tq * 2;
            float bx = 0.0f, by = 0.0f;
            if (bias) { bx = __ldg(bias + gn); by = __ldg(bias + gn + 1); }
            float2 v0 = make_float2(acc[t][nt][0] + bx, acc[t][nt][1] + by);
            float2 v1 = make_float2(acc[t][nt][2] + bx, acc[t][nt][3] + by);
            *(float2*)(C + (size_t)gm * ldc + gn) = v0;
            *(float2*)(C + (size_t)(gm + 8) * ldc + gn) = v1;
        }
}

// ---------------------------------------------------------------------------
// Kernel 1: QKV projections (9 segs), heavy V segs scheduled first.
// ---------------------------------------------------------------------------
__global__ __launch_bounds__(256, 1)
void qkv_mma_kernel(const float* __restrict__ h, WPtrs wp) {
    const int Ks[9]   = {1587,1587,1587, 342,342,342, 100,100,100};
    const int Hoff[9] = { 442, 442, 442, 100,100,100,   0,  0,  0};
    const int s = blockIdx.y;
    gemm_mma_128(h + Hoff[s], INDIM, Ks[s], wp.w[s],
                 g_qkv + s * 128, 1152, nullptr, blockIdx.x * 128);
}

// ---------------------------------------------------------------------------
// Kernel 2: per-(node,unit) attention. E stride 129 -> conflict-free phases.
// ---------------------------------------------------------------------------
__global__ void attn_kernel() {
    extern __shared__ __align__(16) char dsm[];
    float* sm = (float*)dsm;
    float* qs = sm;             // 128
    float* w  = sm + 128;       // 128
    float* E  = sm + 256;       // 128 * 129

    const int n = blockIdx.x;
    const int u = blockIdx.y;   // 0=V, 1=A, 2=T
    const int j = threadIdx.x;

    const float* base = g_qkv + (size_t)n * 1152 + u * 384;
    const float qj = base[j];
    const float kj = base[128 + j];
    const float vj = base[256 + j];

    // log2(e) / sqrt(128)
    const float scale = 1.4426950408889634f / 11.313708498984761f;
    qs[j] = qj * scale;
    __syncthreads();

    float Z = 0.0f;
#pragma unroll 8
    for (int i = 0; i < 128; i++) {
        float e = ex2f(qs[i] * kj);
        Z += e;
        E[i * 129 + j] = e;
    }
    w[j] = vj / Z;
    __syncthreads();

    float out0 = 0.0f, out1 = 0.0f, out2 = 0.0f, out3 = 0.0f;
    const float* Er = E + j * 129;
#pragma unroll 8
    for (int t = 0; t < 128; t += 4) {
        out0 += Er[t + 0] * w[t + 0];
        out1 += Er[t + 1] * w[t + 1];
        out2 += Er[t + 2] * w[t + 2];
        out3 += Er[t + 3] * w[t + 3];
    }
    const int attoff = (2 - u) * 128;  // V->256, A->128, T->0
    g_att[(size_t)n * 384 + attoff + j] = (out0 + out1) + (out2 + out3);
}

// ---------------------------------------------------------------------------
// Kernel 3: out = att @ Wln.T + bln (K = 384), same GEMM template.
// ---------------------------------------------------------------------------
__global__ __launch_bounds__(256, 1)
void out_mma_kernel(const float* __restrict__ Wln, const float* __restrict__ bln,
                    float* __restrict__ out) {
    gemm_mma_128(g_att, 384, 384, Wln, out, 128, bln, blockIdx.x * 128);
}

// ---------------------------------------------------------------------------
// Input order: 0 g, 1 h, 2 WqT, 3 WkT, 4 WvT, 5 WqA, 6 WkA, 7 WvA,
//              8 WqV, 9 WkV, 10 WvV, 11 Wln, 12 bln
// ---------------------------------------------------------------------------
extern "C" void kernel_launch(void* const* d_in, const int* in_sizes, int n_in,
                              void* d_out, int out_size) {
    const float* h = (const float*)d_in[1];
    WPtrs wp;
    wp.w[0] = (const float*)d_in[8];   // WqV (heavy segs first)
    wp.w[1] = (const float*)d_in[9];   // WkV
    wp.w[2] = (const float*)d_in[10];  // WvV
    wp.w[3] = (const float*)d_in[5];   // WqA
    wp.w[4] = (const float*)d_in[6];   // WkA
    wp.w[5] = (const float*)d_in[7];   // WvA
    wp.w[6] = (const float*)d_in[2];   // WqT
    wp.w[7] = (const float*)d_in[3];   // WkT
    wp.w[8] = (const float*)d_in[4];   // WvT
    const float* Wln = (const float*)d_in[11];
    const float* bln = (const float*)d_in[12];

    const int gemm_smem = 81920;
    cudaFuncSetAttribute(qkv_mma_kernel, cudaFuncAttributeMaxDynamicSharedMemorySize,
                         gemm_smem);
    qkv_mma_kernel<<<dim3(64, 9), 256, gemm_smem>>>(h, wp);

    const int attn_smem = (128 * 129 + 256) * (int)sizeof(float);  // 67072
    cudaFuncSetAttribute(attn_kernel, cudaFuncAttributeMaxDynamicSharedMemorySize,
                         attn_smem);
    attn_kernel<<<dim3(NROWS, 3), 128, attn_smem>>>();

    cudaFuncSetAttribute(out_mma_kernel, cudaFuncAttributeMaxDynamicSharedMemorySize,
                         gemm_smem);
    out_mma_kernel<<<64, 256, gemm_smem>>>(Wln, bln, (float*)d_out);
}

// round 6
// speedup vs baseline: 2.0428x; 1.0180x over previous
#include <cuda_runtime.h>
#include <cuda_bf16.h>
#include <cstdint>
#include <cstddef>

#define NROWS 8192
#define INDIM 2029
#define HW 2112   // padded plane width: 128(T) + 384(A) + 1600(V)

// Scratch (device globals — no allocation allowed)
__device__ __align__(16) __nv_bfloat16 g_h_hi[NROWS * HW];
__device__ __align__(16) __nv_bfloat16 g_h_lo[NROWS * HW];
__device__ __align__(16) __nv_bfloat16 g_ws[9 * 128 * 4800];   // per-seg B' = [bh|bh|bl]
__device__ __align__(16) __nv_bfloat16 g_wln[128 * 1152];      // Wln B' = [bh|bh|bl]
__device__ float g_qkv[NROWS * 1152];                          // [n][Vq Vk Vv Aq Ak Av Tq Tk Tv]
__device__ __align__(16) __nv_bfloat16 g_att_hi[NROWS * 384];  // [n][T|A|V] hi
__device__ __align__(16) __nv_bfloat16 g_att_lo[NROWS * 384];  // [n][T|A|V] lo

struct WPtrs { const float* w[9]; };

__device__ __forceinline__ float ex2f(float x) {
    float r; asm("ex2.approx.f32 %0, %1;" : "=f"(r) : "f"(x)); return r;
}
__device__ __forceinline__ uint32_t smem_u32(const void* p) {
    uint32_t a;
    asm("{ .reg .u64 t; cvta.to.shared.u64 t, %1; cvt.u32.u64 %0, t; }" : "=r"(a) : "l"(p));
    return a;
}
__device__ __forceinline__ void mma16816(float* c, const uint32_t* a, const uint32_t* b) {
    asm volatile(
        "mma.sync.aligned.m16n8k16.row.col.f32.bf16.bf16.f32 "
        "{%0,%1,%2,%3}, {%4,%5,%6,%7}, {%8,%9}, {%0,%1,%2,%3};"
        : "+f"(c[0]), "+f"(c[1]), "+f"(c[2]), "+f"(c[3])
        : "r"(a[0]), "r"(a[1]), "r"(a[2]), "r"(a[3]), "r"(b[0]), "r"(b[1]));
}
__device__ __forceinline__ void cp16(uint32_t d, const void* s) {
    asm volatile("cp.async.cg.shared.global [%0], [%1], 16;" :: "r"(d), "l"(s));
}
__device__ __forceinline__ void cp_commit() { asm volatile("cp.async.commit_group;" ::: "memory"); }
__device__ __forceinline__ void cp_wait1()  { asm volatile("cp.async.wait_group 1;" ::: "memory"); }

// ---------------------------------------------------------------------------
// Precompute: h -> per-unit hi/lo bf16 planes (zero-padded widths 128/384/1600)
// ---------------------------------------------------------------------------
__global__ __launch_bounds__(256)
void conv_h_kernel(const float* __restrict__ h) {
    const int n = blockIdx.x;
    for (int col = threadIdx.x; col < HW; col += 256) {
        int off, local, F;
        if (col < 128)      { off = 0;   local = col;       F = 100; }
        else if (col < 512) { off = 100; local = col - 128; F = 342; }
        else                { off = 442; local = col - 512; F = 1587; }
        float v = (local < F) ? __ldg(h + (size_t)n * INDIM + off + local) : 0.0f;
        __nv_bfloat16 hi = __float2bfloat16(v);
        __nv_bfloat16 lo = __float2bfloat16(v - __bfloat162float(hi));
        g_h_hi[(size_t)n * HW + col] = hi;
        g_h_lo[(size_t)n * HW + col] = lo;
    }
}

// ---------------------------------------------------------------------------
// Precompute weights: B' = [bh | bh | bl] per seg (and Wln as seg 9)
// ---------------------------------------------------------------------------
__global__ __launch_bounds__(256)
void conv_w_kernel(WPtrs wp, const float* __restrict__ Wln) {
    const int Fs[10]  = {1587,1587,1587, 342,342,342, 100,100,100, 384};
    const int Fps[10] = {1600,1600,1600, 384,384,384, 128,128,128, 384};
    const int d = blockIdx.x, t = blockIdx.y;
    const int F = Fs[t], Fp = Fps[t];
    const float* W = (t < 9) ? wp.w[t] : Wln;
    __nv_bfloat16* dst = (t < 9) ? (g_ws + (size_t)t * 128 * 4800 + (size_t)d * 3 * Fp)
                                 : (g_wln + (size_t)d * 1152);
    for (int k = threadIdx.x; k < 3 * Fp; k += 256) {
        int p = k / Fp, col = k - p * Fp;
        float v = (col < F) ? __ldg(W + (size_t)d * F + col) : 0.0f;
        __nv_bfloat16 hi = __float2bfloat16(v);
        if (p == 2) dst[k] = __float2bfloat16(v - __bfloat162float(hi));
        else        dst[k] = hi;
    }
}

// ---------------------------------------------------------------------------
// Plain bf16 GEMM: C[128 x 128] = A'[128 x 3Kp] * B'[128 x 3Kp]^T (+ bias).
// A' planes: [hi | lo | hi] (selected in loader); B' physically [bh|bh|bl].
// cp.async 3-stage pipeline, smem row stride 144B (conflict-free frags).
// ---------------------------------------------------------------------------
#define ROWB 144
#define TILEB (128 * ROWB)
#define STAGEB (2 * TILEB)
#define GEMM_SMEM (3 * STAGEB)   // 110592

__device__ __forceinline__ void gemm_bf16_128(
    const __nv_bfloat16* __restrict__ Ahi, const __nv_bfloat16* __restrict__ Alo,
    int sA, int Kp,
    const __nv_bfloat16* __restrict__ B, int ldb,
    float* __restrict__ C, int ldc, const float* __restrict__ bias, int n0)
{
    extern __shared__ __align__(16) char dsm[];
    const uint32_t sbase = smem_u32(dsm);
    const int tid = threadIdx.x;
    const int lane = tid & 31, wid = tid >> 5;
    const int wm = wid & 3, wn = wid >> 2;
    const int g4 = lane >> 2, tq = lane & 3;
    const int lr = tid >> 1;
    const int c8 = (tid & 1) * 4;

    const int Kc = Kp >> 6;      // 64-wide chunks per plane
    const int NC = 3 * Kc;

    float acc[2][8][4];
#pragma unroll
    for (int t = 0; t < 2; t++)
#pragma unroll
        for (int nt = 0; nt < 8; nt++)
#pragma unroll
            for (int i = 0; i < 4; i++) acc[t][nt][i] = 0.0f;

    auto issue = [&](int c, int st) {
        int pk = c / Kc;
        int cb = (c - pk * Kc) << 6;
        const __nv_bfloat16* As = ((pk == 1) ? Alo : Ahi)
                                  + (size_t)(n0 + lr) * sA + cb + c8 * 8;
        const __nv_bfloat16* Bs = B + (size_t)lr * ldb + (c << 6) + c8 * 8;
        uint32_t ab = sbase + st * STAGEB + lr * ROWB + c8 * 16;
        uint32_t bb = ab + TILEB;
#pragma unroll
        for (int i = 0; i < 4; i++) {
            cp16(ab + i * 16, As + i * 8);
            cp16(bb + i * 16, Bs + i * 8);
        }
        cp_commit();
    };

    issue(0, 0);
    if (NC > 1) issue(1, 1); else cp_commit();

    for (int c = 0; c < NC; c++) {
        cp_wait1();
        __syncthreads();

        const char* sa = dsm + (c % 3) * STAGEB;
        const char* sb = sa + TILEB;
#pragma unroll
        for (int kk = 0; kk < 4; kk++) {
            const int cb = kk * 32 + tq * 4;
            uint32_t a[2][4];
#pragma unroll
            for (int t = 0; t < 2; t++) {
                int r0 = (wm * 32 + t * 16 + g4) * ROWB;
                a[t][0] = *(const uint32_t*)(sa + r0 + cb);
                a[t][1] = *(const uint32_t*)(sa + r0 + 8 * ROWB + cb);
                a[t][2] = *(const uint32_t*)(sa + r0 + cb + 16);
                a[t][3] = *(const uint32_t*)(sa + r0 + 8 * ROWB + cb + 16);
            }
#pragma unroll
            for (int nt = 0; nt < 8; nt++) {
                int rb = (wn * 64 + nt * 8 + g4) * ROWB;
                uint32_t b[2];
                b[0] = *(const uint32_t*)(sb + rb + cb);
                b[1] = *(const uint32_t*)(sb + rb + cb + 16);
                mma16816(acc[0][nt], a[0], b);
                mma16816(acc[1][nt], a[1], b);
            }
        }

        if (c + 2 < NC) issue(c + 2, (c + 2) % 3);
        else cp_commit();   // empty group keeps wait_group bookkeeping consistent
    }

#pragma unroll
    for (int t = 0; t < 2; t++)
#pragma unroll
        for (int nt = 0; nt < 8; nt++) {
            int gm = n0 + wm * 32 + t * 16 + g4;
            int gn = wn * 64 + nt * 8 + tq * 2;
            float bx = 0.0f, by = 0.0f;
            if (bias) { bx = __ldg(bias + gn); by = __ldg(bias + gn + 1); }
            float2 v0 = make_float2(acc[t][nt][0] + bx, acc[t][nt][1] + by);
            float2 v1 = make_float2(acc[t][nt][2] + bx, acc[t][nt][3] + by);
            *(float2*)(C + (size_t)gm * ldc + gn) = v0;
            *(float2*)(C + (size_t)(gm + 8) * ldc + gn) = v1;
        }
}

// ---------------------------------------------------------------------------
// Kernel 1: QKV projections (9 segs: Vq Vk Vv Aq Ak Av Tq Tk Tv)
// ---------------------------------------------------------------------------
__global__ __launch_bounds__(256, 2)
void qkv_mma_kernel() {
    const int Fps[9] = {1600,1600,1600, 384,384,384, 128,128,128};
    const int ub[9]  = { 512, 512, 512, 128,128,128,   0,  0,  0};
    const int s = blockIdx.y;
    const int Fp = Fps[s];
    gemm_bf16_128(g_h_hi + ub[s], g_h_lo + ub[s], HW, Fp,
                  g_ws + (size_t)s * 128 * 4800, 3 * Fp,
                  g_qkv + s * 128, 1152, nullptr, blockIdx.x * 128);
}

// ---------------------------------------------------------------------------
// Kernel 2: per-(node,unit) attention. E fp32 stride 132 (float4-aligned,
// conflict-free both phases). Emits att as bf16 hi/lo planes.
// ---------------------------------------------------------------------------
#define ATTN_SMEM (1280 + 128 * 132 * 4)   // 68864

__global__ void attn_kernel() {
    extern __shared__ __align__(16) char dsm[];
    float* qs = (float*)dsm;                  // 128 f32
    float* w  = (float*)(dsm + 640);          // 128 f32, 16B-aligned
    float* E  = (float*)(dsm + 1280);         // 128 x 132 f32

    const int n = blockIdx.x;
    const int u = blockIdx.y;   // 0=V, 1=A, 2=T (qkv seg order)
    const int j = threadIdx.x;

    const float* base = g_qkv + (size_t)n * 1152 + u * 384;
    const float qj = base[j];
    const float kj = base[128 + j];
    const float vj = base[256 + j];

    // log2(e) / sqrt(128)
    const float scale = 1.4426950408889634f / 11.313708498984761f;
    qs[j] = qj * scale;
    __syncthreads();

    float Z = 0.0f;
#pragma unroll 8
    for (int i = 0; i < 128; i++) {
        float e = ex2f(qs[i] * kj);
        Z += e;
        E[i * 132 + j] = e;
    }
    w[j] = vj / Z;
    __syncthreads();

    float o0 = 0.0f, o1 = 0.0f, o2 = 0.0f, o3 = 0.0f;
    const float4* Er = (const float4*)(E + j * 132);
    const float4* w4 = (const float4*)w;
#pragma unroll 8
    for (int t = 0; t < 32; t++) {
        float4 e4 = Er[t];
        float4 wv = w4[t];
        o0 += e4.x * wv.x;
        o1 += e4.y * wv.y;
        o2 += e4.z * wv.z;
        o3 += e4.w * wv.w;
    }
    float o = (o0 + o1) + (o2 + o3);

    const int attoff = (2 - u) * 128;   // att layout [T|A|V]
    __nv_bfloat16 hi = __float2bfloat16(o);
    __nv_bfloat16 lo = __float2bfloat16(o - __bfloat162float(hi));
    g_att_hi[(size_t)n * 384 + attoff + j] = hi;
    g_att_lo[(size_t)n * 384 + attoff + j] = lo;
}

// ---------------------------------------------------------------------------
// Kernel 3: out = att @ Wln.T + bln (plain bf16 GEMM, K' = 1152)
// ---------------------------------------------------------------------------
__global__ __launch_bounds__(256, 2)
void out_mma_kernel(const float* __restrict__ bln, float* __restrict__ out) {
    gemm_bf16_128(g_att_hi, g_att_lo, 384, 384, g_wln, 1152,
                  out, 128, bln, blockIdx.x * 128);
}

// ---------------------------------------------------------------------------
// Input order: 0 g, 1 h, 2 WqT, 3 WkT, 4 WvT, 5 WqA, 6 WkA, 7 WvA,
//              8 WqV, 9 WkV, 10 WvV, 11 Wln, 12 bln
// ---------------------------------------------------------------------------
extern "C" void kernel_launch(void* const* d_in, const int* in_sizes, int n_in,
                              void* d_out, int out_size) {
    const float* h = (const float*)d_in[1];
    WPtrs wp;
    wp.w[0] = (const float*)d_in[8];   // WqV
    wp.w[1] = (const float*)d_in[9];   // WkV
    wp.w[2] = (const float*)d_in[10];  // WvV
    wp.w[3] = (const float*)d_in[5];   // WqA
    wp.w[4] = (const float*)d_in[6];   // WkA
    wp.w[5] = (const float*)d_in[7];   // WvA
    wp.w[6] = (const float*)d_in[2];   // WqT
    wp.w[7] = (const float*)d_in[3];   // WkT
    wp.w[8] = (const float*)d_in[4];   // WvT
    const float* Wln = (const float*)d_in[11];
    const float* bln = (const float*)d_in[12];

    conv_h_kernel<<<NROWS, 256>>>(h);
    conv_w_kernel<<<dim3(128, 10), 256>>>(wp, Wln);

    cudaFuncSetAttribute(qkv_mma_kernel, cudaFuncAttributeMaxDynamicSharedMemorySize,
                         GEMM_SMEM);
    qkv_mma_kernel<<<dim3(64, 9), 256, GEMM_SMEM>>>();

    cudaFuncSetAttribute(attn_kernel, cudaFuncAttributeMaxDynamicSharedMemorySize,
                         ATTN_SMEM);
    attn_kernel<<<dim3(NROWS, 3), 128, ATTN_SMEM>>>();

    cudaFuncSetAttribute(out_mma_kernel, cudaFuncAttributeMaxDynamicSharedMemorySize,
                         GEMM_SMEM);
    out_mma_kernel<<<64, 256, GEMM_SMEM>>>(bln, (float*)d_out);
}

// round 7
// speedup vs baseline: 2.7835x; 1.3626x over previous
#include <cuda_runtime.h>
#include <cuda_bf16.h>
#include <cstdint>
#include <cstddef>

#define NROWS 8192
#define INDIM 2029
#define HW 2112   // padded plane width: 128(T) + 384(A) + 1600(V)

// Scratch (device globals — no allocation allowed)
__device__ __align__(16) __nv_bfloat16 g_h_hi[NROWS * HW];
__device__ __align__(16) __nv_bfloat16 g_h_lo[NROWS * HW];
__device__ __align__(16) __nv_bfloat16 g_ws[9 * 128 * 4800];   // per-seg B' = [bh|bh|bl]
__device__ __align__(16) __nv_bfloat16 g_wln[128 * 1152];      // Wln B' = [bh|bh|bl]
__device__ float g_qkv[NROWS * 1152];                          // [n][Vq Vk Vv Aq Ak Av Tq Tk Tv]
__device__ float g_attp[2 * NROWS * 384];                      // j-half partials of att
__device__ __align__(16) __nv_bfloat16 g_att_hi[NROWS * 384];  // [n][T|A|V] hi
__device__ __align__(16) __nv_bfloat16 g_att_lo[NROWS * 384];  // [n][T|A|V] lo

struct WPtrs { const float* w[9]; };

__device__ __forceinline__ float ex2f(float x) {
    float r; asm("ex2.approx.f32 %0, %1;" : "=f"(r) : "f"(x)); return r;
}
__device__ __forceinline__ uint32_t smem_u32(const void* p) {
    uint32_t a;
    asm("{ .reg .u64 t; cvta.to.shared.u64 t, %1; cvt.u32.u64 %0, t; }" : "=r"(a) : "l"(p));
    return a;
}
__device__ __forceinline__ void mma16816(float* c, const uint32_t* a, const uint32_t* b) {
    asm volatile(
        "mma.sync.aligned.m16n8k16.row.col.f32.bf16.bf16.f32 "
        "{%0,%1,%2,%3}, {%4,%5,%6,%7}, {%8,%9}, {%0,%1,%2,%3};"
        : "+f"(c[0]), "+f"(c[1]), "+f"(c[2]), "+f"(c[3])
        : "r"(a[0]), "r"(a[1]), "r"(a[2]), "r"(a[3]), "r"(b[0]), "r"(b[1]));
}
__device__ __forceinline__ void cp16(uint32_t d, const void* s) {
    asm volatile("cp.async.cg.shared.global [%0], [%1], 16;" :: "r"(d), "l"(s));
}
__device__ __forceinline__ void cp_commit() { asm volatile("cp.async.commit_group;" ::: "memory"); }
__device__ __forceinline__ void cp_wait1()  { asm volatile("cp.async.wait_group 1;" ::: "memory"); }

// ---------------------------------------------------------------------------
// Precompute: h -> per-unit hi/lo bf16 planes (zero-padded widths 128/384/1600)
// ---------------------------------------------------------------------------
__global__ __launch_bounds__(256)
void conv_h_kernel(const float* __restrict__ h) {
    const int n = blockIdx.x;
    for (int col = threadIdx.x; col < HW; col += 256) {
        int off, local, F;
        if (col < 128)      { off = 0;   local = col;       F = 100; }
        else if (col < 512) { off = 100; local = col - 128; F = 342; }
        else                { off = 442; local = col - 512; F = 1587; }
        float v = (local < F) ? __ldg(h + (size_t)n * INDIM + off + local) : 0.0f;
        __nv_bfloat16 hi = __float2bfloat16(v);
        __nv_bfloat16 lo = __float2bfloat16(v - __bfloat162float(hi));
        g_h_hi[(size_t)n * HW + col] = hi;
        g_h_lo[(size_t)n * HW + col] = lo;
    }
}

// ---------------------------------------------------------------------------
// Precompute weights: B' = [bh | bh | bl] per seg (and Wln as seg 9)
// ---------------------------------------------------------------------------
__global__ __launch_bounds__(256)
void conv_w_kernel(WPtrs wp, const float* __restrict__ Wln) {
    const int Fs[10]  = {1587,1587,1587, 342,342,342, 100,100,100, 384};
    const int Fps[10] = {1600,1600,1600, 384,384,384, 128,128,128, 384};
    const int d = blockIdx.x, t = blockIdx.y;
    const int F = Fs[t], Fp = Fps[t];
    const float* W = (t < 9) ? wp.w[t] : Wln;
    __nv_bfloat16* dst = (t < 9) ? (g_ws + (size_t)t * 128 * 4800 + (size_t)d * 3 * Fp)
                                 : (g_wln + (size_t)d * 1152);
    for (int k = threadIdx.x; k < 3 * Fp; k += 256) {
        int p = k / Fp, col = k - p * Fp;
        float v = (col < F) ? __ldg(W + (size_t)d * F + col) : 0.0f;
        __nv_bfloat16 hi = __float2bfloat16(v);
        if (p == 2) dst[k] = __float2bfloat16(v - __bfloat162float(hi));
        else        dst[k] = hi;
    }
}

// ---------------------------------------------------------------------------
// Plain bf16 GEMM: C[128 x 128] = A'[128 x 3Kp] * B'[128 x 3Kp]^T (+ bias).
// A' planes: [hi | lo | hi] (selected in loader); B' physically [bh|bh|bl].
// cp.async 3-stage pipeline, smem row stride 144B (conflict-free frags).
// ---------------------------------------------------------------------------
#define ROWB 144
#define TILEB (128 * ROWB)
#define STAGEB (2 * TILEB)
#define GEMM_SMEM (3 * STAGEB)   // 110592

__device__ __forceinline__ void gemm_bf16_128(
    const __nv_bfloat16* __restrict__ Ahi, const __nv_bfloat16* __restrict__ Alo,
    int sA, int Kp,
    const __nv_bfloat16* __restrict__ B, int ldb,
    float* __restrict__ C, int ldc, const float* __restrict__ bias, int n0)
{
    extern __shared__ __align__(16) char dsm[];
    const uint32_t sbase = smem_u32(dsm);
    const int tid = threadIdx.x;
    const int lane = tid & 31, wid = tid >> 5;
    const int wm = wid & 3, wn = wid >> 2;
    const int g4 = lane >> 2, tq = lane & 3;
    const int lr = tid >> 1;
    const int c8 = (tid & 1) * 4;

    const int Kc = Kp >> 6;      // 64-wide chunks per plane
    const int NC = 3 * Kc;

    float acc[2][8][4];
#pragma unroll
    for (int t = 0; t < 2; t++)
#pragma unroll
        for (int nt = 0; nt < 8; nt++)
#pragma unroll
            for (int i = 0; i < 4; i++) acc[t][nt][i] = 0.0f;

    auto issue = [&](int c, int st) {
        int pk = c / Kc;
        int cb = (c - pk * Kc) << 6;
        const __nv_bfloat16* As = ((pk == 1) ? Alo : Ahi)
                                  + (size_t)(n0 + lr) * sA + cb + c8 * 8;
        const __nv_bfloat16* Bs = B + (size_t)lr * ldb + (c << 6) + c8 * 8;
        uint32_t ab = sbase + st * STAGEB + lr * ROWB + c8 * 16;
        uint32_t bb = ab + TILEB;
#pragma unroll
        for (int i = 0; i < 4; i++) {
            cp16(ab + i * 16, As + i * 8);
            cp16(bb + i * 16, Bs + i * 8);
        }
        cp_commit();
    };

    issue(0, 0);
    if (NC > 1) issue(1, 1); else cp_commit();

    for (int c = 0; c < NC; c++) {
        cp_wait1();
        __syncthreads();

        const char* sa = dsm + (c % 3) * STAGEB;
        const char* sb = sa + TILEB;
#pragma unroll
        for (int kk = 0; kk < 4; kk++) {
            const int cb = kk * 32 + tq * 4;
            uint32_t a[2][4];
#pragma unroll
            for (int t = 0; t < 2; t++) {
                int r0 = (wm * 32 + t * 16 + g4) * ROWB;
                a[t][0] = *(const uint32_t*)(sa + r0 + cb);
                a[t][1] = *(const uint32_t*)(sa + r0 + 8 * ROWB + cb);
                a[t][2] = *(const uint32_t*)(sa + r0 + cb + 16);
                a[t][3] = *(const uint32_t*)(sa + r0 + 8 * ROWB + cb + 16);
            }
#pragma unroll
            for (int nt = 0; nt < 8; nt++) {
                int rb = (wn * 64 + nt * 8 + g4) * ROWB;
                uint32_t b[2];
                b[0] = *(const uint32_t*)(sb + rb + cb);
                b[1] = *(const uint32_t*)(sb + rb + cb + 16);
                mma16816(acc[0][nt], a[0], b);
                mma16816(acc[1][nt], a[1], b);
            }
        }

        if (c + 2 < NC) issue(c + 2, (c + 2) % 3);
        else cp_commit();   // empty group keeps wait_group bookkeeping consistent
    }

#pragma unroll
    for (int t = 0; t < 2; t++)
#pragma unroll
        for (int nt = 0; nt < 8; nt++) {
            int gm = n0 + wm * 32 + t * 16 + g4;
            int gn = wn * 64 + nt * 8 + tq * 2;
            float bx = 0.0f, by = 0.0f;
            if (bias) { bx = __ldg(bias + gn); by = __ldg(bias + gn + 1); }
            float2 v0 = make_float2(acc[t][nt][0] + bx, acc[t][nt][1] + by);
            float2 v1 = make_float2(acc[t][nt][2] + bx, acc[t][nt][3] + by);
            *(float2*)(C + (size_t)gm * ldc + gn) = v0;
            *(float2*)(C + (size_t)(gm + 8) * ldc + gn) = v1;
        }
}

// ---------------------------------------------------------------------------
// Kernel 1: QKV projections (9 segs: Vq Vk Vv Aq Ak Av Tq Tk Tv)
// ---------------------------------------------------------------------------
__global__ __launch_bounds__(256, 2)
void qkv_mma_kernel() {
    const int Fps[9] = {1600,1600,1600, 384,384,384, 128,128,128};
    const int ub[9]  = { 512, 512, 512, 128,128,128,   0,  0,  0};
    const int s = blockIdx.y;
    const int Fp = Fps[s];
    gemm_bf16_128(g_h_hi + ub[s], g_h_lo + ub[s], HW, Fp,
                  g_ws + (size_t)s * 128 * 4800, 3 * Fp,
                  g_qkv + s * 128, 1152, nullptr, blockIdx.x * 128);
}

// ---------------------------------------------------------------------------
// Kernel 2: attention, split over j. Block = (n, u, jhalf): 64 columns.
// E[128 x 64] fp32, stride 68 floats (conflict-free STS + LDS.128).
// smem ~35.3KB -> 6 CTAs/SM (2x occupancy vs full-E kernel).
// ---------------------------------------------------------------------------
#define ESTR 68
#define ATTN_SMEM (1280 + 128 * ESTR * 4)   // 36096

__global__ __launch_bounds__(128)
void attn_kernel() {
    extern __shared__ __align__(16) char dsm[];
    float* qs = (float*)dsm;                  // 128 f32
    float* zp = (float*)(dsm + 512);          // 128 f32 partial Z
    float* w  = (float*)(dsm + 1024);         // 64 f32
    float* E  = (float*)(dsm + 1280);         // 128 x 68 f32

    const int n    = blockIdx.x;
    const int u    = blockIdx.y;   // 0=V, 1=A, 2=T (qkv seg order)
    const int half = blockIdx.z;   // j in [half*64, half*64+64)
    const int t  = threadIdx.x;
    const int j  = t & 63;
    const int ih = t >> 6;

    const float* base = g_qkv + (size_t)n * 1152 + u * 384;

    // log2(e) / sqrt(128)
    const float scale = 1.4426950408889634f / 11.313708498984761f;
    qs[t] = base[t] * scale;
    const float kj = base[128 + half * 64 + j];
    __syncthreads();

    // Phase 1: E columns + partial Z (thread covers 64 i's of its column)
    float z0 = 0.0f, z1 = 0.0f;
    const int i0 = ih * 64;
#pragma unroll 8
    for (int ii = 0; ii < 64; ii += 2) {
        float e0 = ex2f(qs[i0 + ii] * kj);
        float e1 = ex2f(qs[i0 + ii + 1] * kj);
        E[(i0 + ii) * ESTR + j] = e0;
        E[(i0 + ii + 1) * ESTR + j] = e1;
        z0 += e0;
        z1 += e1;
    }
    zp[t] = z0 + z1;
    __syncthreads();
    if (t < 64) {
        float Z = zp[t] + zp[t + 64];
        w[t] = base[256 + half * 64 + t] / Z;
    }
    __syncthreads();

    // Phase 2: row dot (thread = output row i = t), 16 float4 pairs
    float o0 = 0.0f, o1 = 0.0f, o2 = 0.0f, o3 = 0.0f;
    const float4* Er = (const float4*)(E + t * ESTR);
    const float4* w4 = (const float4*)w;
#pragma unroll
    for (int q = 0; q < 16; q++) {
        float4 e4 = Er[q];
        float4 wv = w4[q];
        o0 += e4.x * wv.x;
        o1 += e4.y * wv.y;
        o2 += e4.z * wv.z;
        o3 += e4.w * wv.w;
    }
    float o = (o0 + o1) + (o2 + o3);

    const int attoff = (2 - u) * 128;   // att layout [T|A|V]
    g_attp[(size_t)half * (NROWS * 384) + (size_t)n * 384 + attoff + t] = o;
}

// ---------------------------------------------------------------------------
// Kernel 2b: sum the two j-half partials, emit att hi/lo bf16 planes.
// ---------------------------------------------------------------------------
__global__ __launch_bounds__(256)
void att_fix_kernel() {
    const int idx = blockIdx.x * 256 + threadIdx.x;   // NROWS*384 total
    float o = g_attp[idx] + g_attp[idx + NROWS * 384];
    __nv_bfloat16 hi = __float2bfloat16(o);
    __nv_bfloat16 lo = __float2bfloat16(o - __bfloat162float(hi));
    g_att_hi[idx] = hi;
    g_att_lo[idx] = lo;
}

// ---------------------------------------------------------------------------
// Kernel 3: out = att @ Wln.T + bln (plain bf16 GEMM, K' = 1152)
// ---------------------------------------------------------------------------
__global__ __launch_bounds__(256, 2)
void out_mma_kernel(const float* __restrict__ bln, float* __restrict__ out) {
    gemm_bf16_128(g_att_hi, g_att_lo, 384, 384, g_wln, 1152,
                  out, 128, bln, blockIdx.x * 128);
}

// ---------------------------------------------------------------------------
// Input order: 0 g, 1 h, 2 WqT, 3 WkT, 4 WvT, 5 WqA, 6 WkA, 7 WvA,
//              8 WqV, 9 WkV, 10 WvV, 11 Wln, 12 bln
// ---------------------------------------------------------------------------
extern "C" void kernel_launch(void* const* d_in, const int* in_sizes, int n_in,
                              void* d_out, int out_size) {
    const float* h = (const float*)d_in[1];
    WPtrs wp;
    wp.w[0] = (const float*)d_in[8];   // WqV
    wp.w[1] = (const float*)d_in[9];   // WkV
    wp.w[2] = (const float*)d_in[10];  // WvV
    wp.w[3] = (const float*)d_in[5];   // WqA
    wp.w[4] = (const float*)d_in[6];   // WkA
    wp.w[5] = (const float*)d_in[7];   // WvA
    wp.w[6] = (const float*)d_in[2];   // WqT
    wp.w[7] = (const float*)d_in[3];   // WkT
    wp.w[8] = (const float*)d_in[4];   // WvT
    const float* Wln = (const float*)d_in[11];
    const float* bln = (const float*)d_in[12];

    conv_h_kernel<<<NROWS, 256>>>(h);
    conv_w_kernel<<<dim3(128, 10), 256>>>(wp, Wln);

    cudaFuncSetAttribute(qkv_mma_kernel, cudaFuncAttributeMaxDynamicSharedMemorySize,
                         GEMM_SMEM);
    qkv_mma_kernel<<<dim3(64, 9), 256, GEMM_SMEM>>>();

    cudaFuncSetAttribute(attn_kernel, cudaFuncAttributeMaxDynamicSharedMemorySize,
                         ATTN_SMEM);
    attn_kernel<<<dim3(NROWS, 3, 2), 128, ATTN_SMEM>>>();

    att_fix_kernel<<<(NROWS * 384) / 256, 256>>>();

    cudaFuncSetAttribute(out_mma_kernel, cudaFuncAttributeMaxDynamicSharedMemorySize,
                         GEMM_SMEM);
    out_mma_kernel<<<64, 256, GEMM_SMEM>>>(bln, (float*)d_out);
}

// round 8
// speedup vs baseline: 2.8190x; 1.0127x over previous
#include <cuda_runtime.h>
#include <cuda_bf16.h>
#include <cstdint>
#include <cstddef>

#define NROWS 8192
#define INDIM 2029
#define HW 2112   // padded plane width: 128(T) + 384(A) + 1600(V)

// Scratch (device globals — no allocation allowed)
__device__ __align__(16) __nv_bfloat16 g_h_hi[NROWS * HW];
__device__ __align__(16) __nv_bfloat16 g_h_lo[NROWS * HW];
__device__ __align__(16) __nv_bfloat16 g_ws[9 * 128 * 4800];   // per-seg B' = [bh|bh|bl]
__device__ __align__(16) __nv_bfloat16 g_wln[128 * 1152];      // Wln B' = [bh|bh|bl]
__device__ float g_qkv[NROWS * 1152];                          // [n][Vq Vk Vv Aq Ak Av Tq Tk Tv]
__device__ float g_qkv2[NROWS * 384];                          // V segs, K-chunks [38,75) partial
__device__ float g_attp[2 * NROWS * 384];                      // j-half partials of att
__device__ __align__(16) __nv_bfloat16 g_att_hi[NROWS * 384];  // [n][T|A|V] hi
__device__ __align__(16) __nv_bfloat16 g_att_lo[NROWS * 384];  // [n][T|A|V] lo

struct WPtrs { const float* w[9]; };

__device__ __forceinline__ float ex2f(float x) {
    float r; asm("ex2.approx.f32 %0, %1;" : "=f"(r) : "f"(x)); return r;
}
__device__ __forceinline__ uint32_t smem_u32(const void* p) {
    uint32_t a;
    asm("{ .reg .u64 t; cvta.to.shared.u64 t, %1; cvt.u32.u64 %0, t; }" : "=r"(a) : "l"(p));
    return a;
}
__device__ __forceinline__ void mma16816(float* c, const uint32_t* a, const uint32_t* b) {
    asm volatile(
        "mma.sync.aligned.m16n8k16.row.col.f32.bf16.bf16.f32 "
        "{%0,%1,%2,%3}, {%4,%5,%6,%7}, {%8,%9}, {%0,%1,%2,%3};"
        : "+f"(c[0]), "+f"(c[1]), "+f"(c[2]), "+f"(c[3])
        : "r"(a[0]), "r"(a[1]), "r"(a[2]), "r"(a[3]), "r"(b[0]), "r"(b[1]));
}
__device__ __forceinline__ void cp16(uint32_t d, const void* s) {
    asm volatile("cp.async.cg.shared.global [%0], [%1], 16;" :: "r"(d), "l"(s));
}
__device__ __forceinline__ void cp_commit() { asm volatile("cp.async.commit_group;" ::: "memory"); }
__device__ __forceinline__ void cp_wait1()  { asm volatile("cp.async.wait_group 1;" ::: "memory"); }

// ---------------------------------------------------------------------------
// Precompute: h -> per-unit hi/lo bf16 planes (zero-padded widths 128/384/1600)
// ---------------------------------------------------------------------------
__global__ __launch_bounds__(256)
void conv_h_kernel(const float* __restrict__ h) {
    const int n = blockIdx.x;
    for (int col = threadIdx.x; col < HW; col += 256) {
        int off, local, F;
        if (col < 128)      { off = 0;   local = col;       F = 100; }
        else if (col < 512) { off = 100; local = col - 128; F = 342; }
        else                { off = 442; local = col - 512; F = 1587; }
        float v = (local < F) ? __ldg(h + (size_t)n * INDIM + off + local) : 0.0f;
        __nv_bfloat16 hi = __float2bfloat16(v);
        __nv_bfloat16 lo = __float2bfloat16(v - __bfloat162float(hi));
        g_h_hi[(size_t)n * HW + col] = hi;
        g_h_lo[(size_t)n * HW + col] = lo;
    }
}

// ---------------------------------------------------------------------------
// Precompute weights: B' = [bh | bh | bl] per seg (and Wln as seg 9)
// ---------------------------------------------------------------------------
__global__ __launch_bounds__(256)
void conv_w_kernel(WPtrs wp, const float* __restrict__ Wln) {
    const int Fs[10]  = {1587,1587,1587, 342,342,342, 100,100,100, 384};
    const int Fps[10] = {1600,1600,1600, 384,384,384, 128,128,128, 384};
    const int d = blockIdx.x, t = blockIdx.y;
    const int F = Fs[t], Fp = Fps[t];
    const float* W = (t < 9) ? wp.w[t] : Wln;
    __nv_bfloat16* dst = (t < 9) ? (g_ws + (size_t)t * 128 * 4800 + (size_t)d * 3 * Fp)
                                 : (g_wln + (size_t)d * 1152);
    for (int k = threadIdx.x; k < 3 * Fp; k += 256) {
        int p = k / Fp, col = k - p * Fp;
        float v = (col < F) ? __ldg(W + (size_t)d * F + col) : 0.0f;
        __nv_bfloat16 hi = __float2bfloat16(v);
        if (p == 2) dst[k] = __float2bfloat16(v - __bfloat162float(hi));
        else        dst[k] = hi;
    }
}

// ---------------------------------------------------------------------------
// Plain bf16 GEMM: C[128 x 128] = A'[128 x 3Kp] * B'[128 x 3Kp]^T (+ bias),
// over chunk range [c0, c1). A' planes: [hi | lo | hi] (selected in loader);
// B' physically [bh|bh|bl]. cp.async 3-stage pipeline, smem row stride 144B.
// ---------------------------------------------------------------------------
#define ROWB 144
#define TILEB (128 * ROWB)
#define STAGEB (2 * TILEB)
#define GEMM_SMEM (3 * STAGEB)   // 110592

__device__ __forceinline__ void gemm_bf16_128(
    const __nv_bfloat16* __restrict__ Ahi, const __nv_bfloat16* __restrict__ Alo,
    int sA, int Kp,
    const __nv_bfloat16* __restrict__ B, int ldb,
    float* __restrict__ C, int ldc, const float* __restrict__ bias, int n0,
    int c0, int c1)
{
    extern __shared__ __align__(16) char dsm[];
    const uint32_t sbase = smem_u32(dsm);
    const int tid = threadIdx.x;
    const int lane = tid & 31, wid = tid >> 5;
    const int wm = wid & 3, wn = wid >> 2;
    const int g4 = lane >> 2, tq = lane & 3;
    const int lr = tid >> 1;
    const int c8 = (tid & 1) * 4;

    const int Kc = Kp >> 6;      // 64-wide chunks per plane
    const int NC = c1 - c0;

    float acc[2][8][4];
#pragma unroll
    for (int t = 0; t < 2; t++)
#pragma unroll
        for (int nt = 0; nt < 8; nt++)
#pragma unroll
            for (int i = 0; i < 4; i++) acc[t][nt][i] = 0.0f;

    auto issue = [&](int c, int st) {
        int pk = c / Kc;
        int cb = (c - pk * Kc) << 6;
        const __nv_bfloat16* As = ((pk == 1) ? Alo : Ahi)
                                  + (size_t)(n0 + lr) * sA + cb + c8 * 8;
        const __nv_bfloat16* Bs = B + (size_t)lr * ldb + (c << 6) + c8 * 8;
        uint32_t ab = sbase + st * STAGEB + lr * ROWB + c8 * 16;
        uint32_t bb = ab + TILEB;
#pragma unroll
        for (int i = 0; i < 4; i++) {
            cp16(ab + i * 16, As + i * 8);
            cp16(bb + i * 16, Bs + i * 8);
        }
        cp_commit();
    };

    issue(c0, 0);
    if (NC > 1) issue(c0 + 1, 1); else cp_commit();

    for (int ci = 0; ci < NC; ci++) {
        cp_wait1();
        __syncthreads();

        const char* sa = dsm + (ci % 3) * STAGEB;
        const char* sb = sa + TILEB;
#pragma unroll
        for (int kk = 0; kk < 4; kk++) {
            const int cb = kk * 32 + tq * 4;
            uint32_t a[2][4];
#pragma unroll
            for (int t = 0; t < 2; t++) {
                int r0 = (wm * 32 + t * 16 + g4) * ROWB;
                a[t][0] = *(const uint32_t*)(sa + r0 + cb);
                a[t][1] = *(const uint32_t*)(sa + r0 + 8 * ROWB + cb);
                a[t][2] = *(const uint32_t*)(sa + r0 + cb + 16);
                a[t][3] = *(const uint32_t*)(sa + r0 + 8 * ROWB + cb + 16);
            }
#pragma unroll
            for (int nt = 0; nt < 8; nt++) {
                int rb = (wn * 64 + nt * 8 + g4) * ROWB;
                uint32_t b[2];
                b[0] = *(const uint32_t*)(sb + rb + cb);
                b[1] = *(const uint32_t*)(sb + rb + cb + 16);
                mma16816(acc[0][nt], a[0], b);
                mma16816(acc[1][nt], a[1], b);
            }
        }

        if (ci + 2 < NC) issue(c0 + ci + 2, (ci + 2) % 3);
        else cp_commit();   // empty group keeps wait_group bookkeeping consistent
    }

#pragma unroll
    for (int t = 0; t < 2; t++)
#pragma unroll
        for (int nt = 0; nt < 8; nt++) {
            int gm = n0 + wm * 32 + t * 16 + g4;
            int gn = wn * 64 + nt * 8 + tq * 2;
            float bx = 0.0f, by = 0.0f;
            if (bias) { bx = __ldg(bias + gn); by = __ldg(bias + gn + 1); }
            float2 v0 = make_float2(acc[t][nt][0] + bx, acc[t][nt][1] + by);
            float2 v1 = make_float2(acc[t][nt][2] + bx, acc[t][nt][3] + by);
            *(float2*)(C + (size_t)gm * ldc + gn) = v0;
            *(float2*)(C + (size_t)(gm + 8) * ldc + gn) = v1;
        }
}

// ---------------------------------------------------------------------------
// Kernel 1: QKV projections. V segs (s<3) split in K over blockIdx.z:
// z=0 -> chunks [0,38) into g_qkv; z=1 -> chunks [38,75) into g_qkv2.
// ---------------------------------------------------------------------------
__global__ __launch_bounds__(256, 2)
void qkv_mma_kernel() {
    const int Fps[9] = {1600,1600,1600, 384,384,384, 128,128,128};
    const int ub[9]  = { 512, 512, 512, 128,128,128,   0,  0,  0};
    const int s = blockIdx.y, z = blockIdx.z;
    const int Fp = Fps[s];
    const int NC = 3 * (Fp >> 6);

    int c0 = 0, c1 = NC, ldc = 1152;
    float* C = g_qkv + s * 128;
    if (s < 3) {
        if (z == 0) c1 = 38;
        else { c0 = 38; C = g_qkv2 + s * 128; ldc = 384; }
    } else if (z == 1) {
        return;
    }
    gemm_bf16_128(g_h_hi + ub[s], g_h_lo + ub[s], HW, Fp,
                  g_ws + (size_t)s * 128 * 4800, 3 * Fp,
                  C, ldc, nullptr, blockIdx.x * 128, c0, c1);
}

// ---------------------------------------------------------------------------
// Kernel 2: attention, split over j. Block = (n, u, jhalf): 64 columns.
// E[128 x 64] fp32, stride 68 floats (conflict-free STS + LDS.128).
// u==0 (V) sums the two qkv K-partials. qs read as float4 broadcasts.
// ---------------------------------------------------------------------------
#define ESTR 68
#define ATTN_SMEM (1280 + 128 * ESTR * 4)   // 36096

__global__ __launch_bounds__(128)
void attn_kernel() {
    extern __shared__ __align__(16) char dsm[];
    float* qs = (float*)dsm;                  // 128 f32
    float* zp = (float*)(dsm + 512);          // 128 f32 partial Z
    float* w  = (float*)(dsm + 1024);         // 64 f32
    float* E  = (float*)(dsm + 1280);         // 128 x 68 f32

    const int n    = blockIdx.x;
    const int u    = blockIdx.y;   // 0=V, 1=A, 2=T (qkv seg order)
    const int half = blockIdx.z;   // j in [half*64, half*64+64)
    const int t  = threadIdx.x;
    const int j  = t & 63;
    const int ih = t >> 6;

    const float* base  = g_qkv  + (size_t)n * 1152 + u * 384;
    const float* base2 = g_qkv2 + (size_t)n * 384;

    // log2(e) / sqrt(128)
    const float scale = 1.4426950408889634f / 11.313708498984761f;
    float qraw = base[t];
    float kraw = base[128 + half * 64 + j];
    if (u == 0) {
        qraw += base2[t];
        kraw += base2[128 + half * 64 + j];
    }
    qs[t] = qraw * scale;
    const float kj = kraw;
    __syncthreads();

    // Phase 1: E columns + partial Z; qs read as 16B broadcasts
    float z0 = 0.0f, z1 = 0.0f, z2 = 0.0f, z3 = 0.0f;
    const int i0 = ih * 64;
    const float4* qs4 = (const float4*)(qs + i0);
    float* Ecol = E + (size_t)i0 * ESTR + j;
#pragma unroll
    for (int q = 0; q < 16; q++) {
        float4 qv = qs4[q];
        float e0 = ex2f(qv.x * kj);
        float e1 = ex2f(qv.y * kj);
        float e2 = ex2f(qv.z * kj);
        float e3 = ex2f(qv.w * kj);
        Ecol[(q * 4 + 0) * ESTR] = e0;
        Ecol[(q * 4 + 1) * ESTR] = e1;
        Ecol[(q * 4 + 2) * ESTR] = e2;
        Ecol[(q * 4 + 3) * ESTR] = e3;
        z0 += e0; z1 += e1; z2 += e2; z3 += e3;
    }
    zp[t] = (z0 + z1) + (z2 + z3);
    __syncthreads();
    if (t < 64) {
        float Z = zp[t] + zp[t + 64];
        float vraw = base[256 + half * 64 + t];
        if (u == 0) vraw += base2[256 + half * 64 + t];
        w[t] = vraw / Z;
    }
    __syncthreads();

    // Phase 2: row dot (thread = output row i = t), 16 float4 pairs
    float o0 = 0.0f, o1 = 0.0f, o2 = 0.0f, o3 = 0.0f;
    const float4* Er = (const float4*)(E + t * ESTR);
    const float4* w4 = (const float4*)w;
#pragma unroll
    for (int q = 0; q < 16; q++) {
        float4 e4 = Er[q];
        float4 wv = w4[q];
        o0 += e4.x * wv.x;
        o1 += e4.y * wv.y;
        o2 += e4.z * wv.z;
        o3 += e4.w * wv.w;
    }
    float o = (o0 + o1) + (o2 + o3);

    const int attoff = (2 - u) * 128;   // att layout [T|A|V]
    g_attp[(size_t)half * (NROWS * 384) + (size_t)n * 384 + attoff + t] = o;
}

// ---------------------------------------------------------------------------
// Kernel 2b: sum the two j-half partials, emit att hi/lo bf16 planes.
// ---------------------------------------------------------------------------
__global__ __launch_bounds__(256)
void att_fix_kernel() {
    const int idx = blockIdx.x * 256 + threadIdx.x;   // NROWS*384 total
    float o = g_attp[idx] + g_attp[idx + NROWS * 384];
    __nv_bfloat16 hi = __float2bfloat16(o);
    __nv_bfloat16 lo = __float2bfloat16(o - __bfloat162float(hi));
    g_att_hi[idx] = hi;
    g_att_lo[idx] = lo;
}

// ---------------------------------------------------------------------------
// Kernel 3: out = att @ Wln.T + bln (plain bf16 GEMM, K' = 1152)
// ---------------------------------------------------------------------------
__global__ __launch_bounds__(256, 2)
void out_mma_kernel(const float* __restrict__ bln, float* __restrict__ out) {
    gemm_bf16_128(g_att_hi, g_att_lo, 384, 384, g_wln, 1152,
                  out, 128, bln, blockIdx.x * 128, 0, 18);
}

// ---------------------------------------------------------------------------
// Input order: 0 g, 1 h, 2 WqT, 3 WkT, 4 WvT, 5 WqA, 6 WkA, 7 WvA,
//              8 WqV, 9 WkV, 10 WvV, 11 Wln, 12 bln
// ---------------------------------------------------------------------------
extern "C" void kernel_launch(void* const* d_in, const int* in_sizes, int n_in,
                              void* d_out, int out_size) {
    const float* h = (const float*)d_in[1];
    WPtrs wp;
    wp.w[0] = (const float*)d_in[8];   // WqV
    wp.w[1] = (const float*)d_in[9];   // WkV
    wp.w[2] = (const float*)d_in[10];  // WvV
    wp.w[3] = (const float*)d_in[5];   // WqA
    wp.w[4] = (const float*)d_in[6];   // WkA
    wp.w[5] = (const float*)d_in[7];   // WvA
    wp.w[6] = (const float*)d_in[2];   // WqT
    wp.w[7] = (const float*)d_in[3];   // WkT
    wp.w[8] = (const float*)d_in[4];   // WvT
    const float* Wln = (const float*)d_in[11];
    const float* bln = (const float*)d_in[12];

    conv_h_kernel<<<NROWS, 256>>>(h);
    conv_w_kernel<<<dim3(128, 10), 256>>>(wp, Wln);

    cudaFuncSetAttribute(qkv_mma_kernel, cudaFuncAttributeMaxDynamicSharedMemorySize,
                         GEMM_SMEM);
    qkv_mma_kernel<<<dim3(64, 9, 2), 256, GEMM_SMEM>>>();

    cudaFuncSetAttribute(attn_kernel, cudaFuncAttributeMaxDynamicSharedMemorySize,
                         ATTN_SMEM);
    attn_kernel<<<dim3(NROWS, 3, 2), 128, ATTN_SMEM>>>();

    att_fix_kernel<<<(NROWS * 384) / 256, 256>>>();

    cudaFuncSetAttribute(out_mma_kernel, cudaFuncAttributeMaxDynamicSharedMemorySize,
                         GEMM_SMEM);
    out_mma_kernel<<<64, 256, GEMM_SMEM>>>(bln, (float*)d_out);
}